// round 2
// baseline (speedup 1.0000x reference)
#include <cuda_runtime.h>

#define BATCH   4096
#define L_IN    16384
#define L_OUT   2044
#define TAPS    36      // composite kernel length: 5 + 2*5 + 4*5 + 1
#define NOUT    4       // outputs per thread
#define TASKS_PER_ROW (L_OUT / NOUT)          // 511
#define NTASKS  (BATCH * TASKS_PER_ROW)       // 2,093,056
#define TPB     256
#define NBLOCKS (NTASKS / TPB)                // 8176 exactly

__global__ __launch_bounds__(TPB) void encoder_fused_kernel(
    const float* __restrict__ x,
    const float* __restrict__ w1, const float* __restrict__ b1,
    const float* __restrict__ w2, const float* __restrict__ b2,
    const float* __restrict__ w3, const float* __restrict__ b3,
    float* __restrict__ out)
{
    __shared__ float Wsh[TAPS];
    __shared__ float Csh;

    const int tid = threadIdx.x;

    // ---- composite weight + bias (per block; tiny) ----
    if (tid < TAPS) {
        float s = 0.0f;
        #pragma unroll
        for (int c = 0; c < 6; c++) {
            #pragma unroll
            for (int b = 0; b < 6; b++) {
                int a = tid - 4 * c - 2 * b;
                if (a >= 0 && a < 6)
                    s += w1[a] * w2[b] * w3[c];
            }
        }
        Wsh[tid] = s;
    }
    if (tid == 0) {
        float S2 = 0.0f, S3 = 0.0f;
        #pragma unroll
        for (int i = 0; i < 6; i++) { S2 += w2[i]; S3 += w3[i]; }
        Csh = b3[0] + b2[0] * S3 + b1[0] * S2 * S3;
    }
    __syncthreads();

    const int task = blockIdx.x * TPB + tid;
    const int row  = task / TASKS_PER_ROW;
    const int trow = task - row * TASKS_PER_ROW;   // task index within row
    const int j0   = trow * NOUT;                  // first output index

    // Input window: x[row, 8*j0 .. 8*j0 + 8*(NOUT-1) + 35] = 60 floats = 15 float4,
    // 16B-aligned because 8*j0 is a multiple of 8 floats.
    const float4* xr = reinterpret_cast<const float4*>(x + (size_t)row * L_IN) + trow * (2 * NOUT);

    float f[60];
    #pragma unroll
    for (int i = 0; i < 15; i++) {
        float4 v = __ldg(xr + i);
        f[4 * i + 0] = v.x;
        f[4 * i + 1] = v.y;
        f[4 * i + 2] = v.z;
        f[4 * i + 3] = v.w;
    }

    const float C = Csh;
    float4 o;
    float acc[NOUT];
    #pragma unroll
    for (int k = 0; k < NOUT; k++) {
        float a = C;
        #pragma unroll
        for (int t = 0; t < TAPS; t++)
            a = fmaf(Wsh[t], f[8 * k + t], a);
        acc[k] = a;
    }
    o.x = acc[0]; o.y = acc[1]; o.z = acc[2]; o.w = acc[3];

    // Output: row stride 2044 (multiple of 4) -> float4 store is aligned.
    float4* op = reinterpret_cast<float4*>(out + (size_t)row * L_OUT + j0);
    *op = o;
}

extern "C" void kernel_launch(void* const* d_in, const int* in_sizes, int n_in,
                              void* d_out, int out_size)
{
    const float* x  = (const float*)d_in[0];
    const float* w1 = (const float*)d_in[1];
    const float* b1 = (const float*)d_in[2];
    const float* w2 = (const float*)d_in[3];
    const float* b2 = (const float*)d_in[4];
    const float* w3 = (const float*)d_in[5];
    const float* b3 = (const float*)d_in[6];
    float* out = (float*)d_out;

    encoder_fused_kernel<<<NBLOCKS, TPB>>>(x, w1, b1, w2, b2, w3, b3, out);
}

// round 4
// speedup vs baseline: 1.9234x; 1.9234x over previous
#include <cuda_runtime.h>

#define BATCH   4096
#define L_IN    16384
#define L_OUT   2044
#define TAPS    36          // composite kernel: 5 + 2*5 + 4*5 + 1
#define NOUT    4           // outputs per task
#define TASKS_PER_ROW (L_OUT / NOUT)     // 511
#define TPB     256
#define TILE_IN 8224        // floats staged per tile (257 * 32)
#define PADF(i) ((i) + 4 * ((i) >> 5))   // 4-float pad per 32 floats, keeps 16B align
#define SMEM_FLOATS (TILE_IN + 4 * (TILE_IN / 32))   // 9252

__global__ __launch_bounds__(TPB) void encoder_fused_kernel(
    const float* __restrict__ x,
    const float* __restrict__ w1, const float* __restrict__ b1,
    const float* __restrict__ w2, const float* __restrict__ b2,
    const float* __restrict__ w3, const float* __restrict__ b3,
    float* __restrict__ out)
{
    __shared__ float xs[SMEM_FLOATS];
    __shared__ float Wsh[TAPS];
    __shared__ float Csh;

    const int tid  = threadIdx.x;
    const int row  = blockIdx.x >> 1;
    const int tile = blockIdx.x & 1;
    const int tileStart = tile * 8192;      // float offset of this tile in the row

    // ---- composite weight + bias (tiny, per block) ----
    if (tid < TAPS) {
        float s = 0.0f;
        #pragma unroll
        for (int c = 0; c < 6; c++) {
            #pragma unroll
            for (int b = 0; b < 6; b++) {
                int a = tid - 4 * c - 2 * b;
                if (a >= 0 && a < 6)
                    s += w1[a] * w2[b] * w3[c];
            }
        }
        Wsh[tid] = s;
    }
    if (tid == 0) {
        float S2 = 0.0f, S3 = 0.0f;
        #pragma unroll
        for (int i = 0; i < 6; i++) { S2 += w2[i]; S3 += w3[i]; }
        Csh = b3[0] + b2[0] * S3 + b1[0] * S2 * S3;
    }

    // ---- cooperative coalesced load into padded smem ----
    const float4* src = reinterpret_cast<const float4*>(x + (size_t)row * L_IN + tileStart);
    const int nQuad = min(TILE_IN >> 2, (L_IN - tileStart) >> 2);  // 2056 or 2048
    for (int q = tid; q < nQuad; q += TPB) {
        float4 v = __ldg(src + q);
        int ip = 4 * q + 4 * (q >> 3);    // PADF(4q)
        *reinterpret_cast<float4*>(&xs[ip]) = v;
    }
    __syncthreads();

    // ---- compute: each thread = 4 consecutive outputs ----
    const int task = tile * TPB + tid;          // 0..511 (511 is invalid)
    if (task < TASKS_PER_ROW) {
        // local window start = 32*tid floats (60 floats = 15 quads)
        float f[60];
        #pragma unroll
        for (int m = 0; m < 15; m++) {
            int i  = 32 * tid + 4 * m;
            int ip = i + 4 * (i >> 5);
            float4 v = *reinterpret_cast<const float4*>(&xs[ip]);
            f[4 * m + 0] = v.x;
            f[4 * m + 1] = v.y;
            f[4 * m + 2] = v.z;
            f[4 * m + 3] = v.w;
        }

        const float C = Csh;
        float acc[NOUT];
        #pragma unroll
        for (int k = 0; k < NOUT; k++) {
            float a = C;
            #pragma unroll
            for (int t = 0; t < TAPS; t++)
                a = fmaf(Wsh[t], f[8 * k + t], a);
            acc[k] = a;
        }

        float4 o;
        o.x = acc[0]; o.y = acc[1]; o.z = acc[2]; o.w = acc[3];
        float4* op = reinterpret_cast<float4*>(out + (size_t)row * L_OUT + task * NOUT);
        *op = o;
    }
}

extern "C" void kernel_launch(void* const* d_in, const int* in_sizes, int n_in,
                              void* d_out, int out_size)
{
    const float* x  = (const float*)d_in[0];
    const float* w1 = (const float*)d_in[1];
    const float* b1 = (const float*)d_in[2];
    const float* w2 = (const float*)d_in[3];
    const float* b2 = (const float*)d_in[4];
    const float* w3 = (const float*)d_in[5];
    const float* b3 = (const float*)d_in[6];
    float* out = (float*)d_out;

    encoder_fused_kernel<<<BATCH * 2, TPB>>>(x, w1, b1, w2, b2, w3, b3, out);
}